// round 14
// baseline (speedup 1.0000x reference)
#include <cuda_runtime.h>
#include <cstdint>

#define BB 4096
#define NN 8192
#define DD 512
#define RR 4
#define NBLK (BB / 2)    // 2048 blocks: block handles pairs (r, r+B) for 2 r's

__device__ float g_partial[NBLK];
__device__ unsigned int g_ticket;   // zero-init at load; reset by block 0 each run

__device__ __forceinline__ const float* row_ptr(const float* zi, const float* zj, int r) {
    return (r < BB) ? (zi + (size_t)r * DD) : (zj + (size_t)(r - BB) * DD);
}

__device__ __forceinline__ void cp16(uint32_t dst_smem, const float* src) {
    asm volatile("cp.async.cg.shared.global [%0], [%1], 16;"
                 :: "r"(dst_smem), "l"(src));
}

// Block = 4 warps = 4 rows: {r0, r0+B, r1, r1+B}. Warp w's positive partner is
// warp (w^1)'s row (x_buf + x2 shared via smem). All rows staged global->smem
// via cp.async: 20 outstanding 16B copies/lane, structurally immune to the
// ptxas gather-serialization that plagued the register-front-load bodies.
// Tail: st.cg partial + red.release ticket; block 0 = designated deterministic
// reducer (fixed summation order), then resets the ticket for graph replay.
__global__ void __launch_bounds__(128) fused_kernel(const float* __restrict__ zi,
                                                    const float* __restrict__ zj,
                                                    const int* __restrict__ neg_idx,
                                                    float* __restrict__ out) {
    __shared__ float4 x_buf[4][DD / 4];          // 8 KB
    __shared__ float4 n_buf[4][RR][DD / 4];      // 32 KB
    __shared__ float  s_x2[4];
    __shared__ float  s_nll[4];
    __shared__ float  s_ws[4];

    int warp = threadIdx.x >> 5;
    int lane = threadIdx.x & 31;
    int r0   = blockIdx.x * 2 + (warp >> 1);           // pair id
    int row  = (warp & 1) ? (r0 + BB) : r0;            // w0:r0 w1:r0+B w2:r1 w3:r1+B

    int4 nv = *reinterpret_cast<const int4*>(neg_idx + row * RR);
    int neg[RR];
    neg[0] = nv.x + (nv.x >= row ? 1 : 0);
    neg[1] = nv.y + (nv.y >= row ? 1 : 0);
    neg[2] = nv.z + (nv.z >= row ? 1 : 0);
    neg[3] = nv.w + (nv.w >= row ? 1 : 0);

    // ---- stage own row + 4 negatives: 20 cp.async per lane, one group ----
    {
        const float* gx = row_ptr(zi, zj, row);
        uint32_t dx = (uint32_t)__cvta_generic_to_shared(&x_buf[warp][lane]);
#pragma unroll
        for (int k = 0; k < 4; k++)
            cp16(dx + k * 32 * 16, gx + lane * 4 + k * 128);
#pragma unroll
        for (int p = 0; p < RR; p++) {
            const float* gn = row_ptr(zi, zj, neg[p]);
            uint32_t dn = (uint32_t)__cvta_generic_to_shared(&n_buf[warp][p][lane]);
#pragma unroll
            for (int k = 0; k < 4; k++)
                cp16(dn + k * 32 * 16, gn + lane * 4 + k * 128);
        }
        asm volatile("cp.async.commit_group;");
        asm volatile("cp.async.wait_group 0;" ::: "memory");
    }

    // ---- own row into regs + x2 ----
    float4 x[4];
#pragma unroll
    for (int k = 0; k < 4; k++) x[k] = x_buf[warp][lane + 32 * k];

    float x2 = 0.0f;
#pragma unroll
    for (int k = 0; k < 4; k++)
        x2 += x[k].x * x[k].x + x[k].y * x[k].y + x[k].z * x[k].z + x[k].w * x[k].w;
#pragma unroll
    for (int o = 16; o; o >>= 1) x2 += __shfl_xor_sync(0xFFFFFFFFu, x2, o);
    if (lane == 0) s_x2[warp] = x2;

    __syncthreads();   // paired x_buf + s_x2 visible to everyone

    // ---- positive dot: partner = paired warp's x buffer ----
    float pdot = 0.0f;
#pragma unroll
    for (int k = 0; k < 4; k++) {
        float4 b = x_buf[warp ^ 1][lane + 32 * k];
        float4 a = x[k];
        pdot += a.x * b.x + a.y * b.y + a.z * b.z + a.w * b.w;
    }

    // ---- negative dots + norms ----
    float dot[RR], y2[RR];
#pragma unroll
    for (int p = 0; p < RR; p++) {
        float d = 0.0f, n = 0.0f;
#pragma unroll
        for (int k = 0; k < 4; k++) {
            float4 b = n_buf[warp][p][lane + 32 * k];
            float4 a = x[k];
            d += a.x * b.x + a.y * b.y + a.z * b.z + a.w * b.w;
            n += b.x * b.x + b.y * b.y + b.z * b.z + b.w * b.w;
        }
        dot[p] = d;
        y2[p]  = n;
    }

#pragma unroll
    for (int o = 16; o; o >>= 1) {
        pdot += __shfl_xor_sync(0xFFFFFFFFu, pdot, o);
#pragma unroll
        for (int p = 0; p < RR; p++) {
            dot[p] += __shfl_xor_sync(0xFFFFFFFFu, dot[p], o);
            y2[p]  += __shfl_xor_sync(0xFFFFFFFFu, y2[p], o);
        }
    }

    if (lane == 0) {
        const float invT = 1.0f / (0.5f + 1e-8f);
        float rnx = 1.0f / fmaxf(sqrtf(x2), 1e-8f);
        float l[5];
        {
            float rny = 1.0f / fmaxf(sqrtf(s_x2[warp ^ 1]), 1e-8f);
            l[0] = pdot * rnx * rny * invT;
        }
#pragma unroll
        for (int p = 0; p < RR; p++) {
            float rny = 1.0f / fmaxf(sqrtf(y2[p]), 1e-8f);
            l[p + 1] = dot[p] * rnx * rny * invT;
        }
        float m = l[0];
#pragma unroll
        for (int p = 1; p < 5; p++) m = fmaxf(m, l[p]);
        float se = 0.0f;
#pragma unroll
        for (int p = 0; p < 5; p++) se += expf(l[p] - m);
        s_nll[warp] = m + logf(se) - l[0];
    }
    __syncthreads();

    // ---- free tail: partial to L2 + fire-and-forget release ticket ----
    if (threadIdx.x == 0) {
        float partial = s_nll[0] + s_nll[1] + s_nll[2] + s_nll[3];
        asm volatile("st.global.cg.f32 [%0], %1;"
                     :: "l"(&g_partial[blockIdx.x]), "f"(partial) : "memory");
        asm volatile("red.release.gpu.global.add.u32 [%0], 1;"
                     :: "l"(&g_ticket) : "memory");
    }

    // ---- block 0 = designated reducer (deterministic, fixed order) ----
    if (blockIdx.x == 0) {
        if (threadIdx.x == 0) {
            unsigned int v;
            do {
                __nanosleep(64);
                asm volatile("ld.acquire.gpu.global.u32 %0, [%1];"
                             : "=r"(v) : "l"(&g_ticket));
            } while (v < (unsigned int)NBLK);
        }
        __syncthreads();

        float s = 0.0f;
#pragma unroll
        for (int k = 0; k < NBLK / 128; k++) {
            float v;
            asm volatile("ld.global.cg.f32 %0, [%1];"
                         : "=f"(v) : "l"(&g_partial[threadIdx.x + k * 128]));
            s += v;
        }
#pragma unroll
        for (int o = 16; o; o >>= 1) s += __shfl_xor_sync(0xFFFFFFFFu, s, o);
        if (lane == 0) s_ws[warp] = s;
        __syncthreads();
        if (threadIdx.x == 0) {
            float tot = s_ws[0] + s_ws[1] + s_ws[2] + s_ws[3];
            out[0] = tot * (1.0f / (float)NN);
            g_ticket = 0u;   // all blocks arrived; safe reset for next replay
        }
    }
}

extern "C" void kernel_launch(void* const* d_in, const int* in_sizes, int n_in,
                              void* d_out, int out_size) {
    const float* zi      = (const float*)d_in[0];
    const float* zj      = (const float*)d_in[1];
    const int*   neg_idx = (const int*)d_in[2];
    float* out = (float*)d_out;

    fused_kernel<<<NBLK, 128>>>(zi, zj, neg_idx, out);
}